// round 9
// baseline (speedup 1.0000x reference)
#include <cuda_runtime.h>
#include <cuda_bf16.h>
#include <cstdint>

// ---- arch capability: tcgen05 legal only in arch/family-specific device pass ----
#if defined(__CUDA_ARCH__) && (defined(__CUDA_ARCH_SPECIFIC__) || defined(__CUDA_ARCH_FAMILY_SPECIFIC__))
#define HAS_TCGEN05 1
#else
#define HAS_TCGEN05 0
#endif

#define DIM 4096
#define NKB 32              // DIM / 128 (quant tile granularity)
#define BK 128

// ---- fallback (mma.sync int8) tiling — known-good R2 path ----
#define BM 128
#define BN 128
#define A_BYTES (BM * BK)
#define B_BYTES (BN * BK)
#define STAGES 4
#define STAGE_BYTES (A_BYTES + B_BYTES)
#define GEMM_SMEM (2048 + STAGES * STAGE_BYTES)

// ---- tcgen05 bf16 tiling: 256x256 CTA tile, BK=64, 3 stages, 4-CTA multicast cluster ----
#define TC_BM 256
#define TC_BN 256
#define NK64 64                          // DIM / 64
#define A64_BYTES (128 * 64 * 2)         // 16384 per M-half per k64
#define B64_BYTES (256 * 64 * 2)         // 32768 per k64
#define TC_STAGE_BYTES (2 * A64_BYTES + B64_BYTES)   // 65536
#define TC_NSTAGE 3
#define TC_SMEM (2048 + TC_NSTAGE * TC_STAGE_BYTES)  // 198656

// legacy per-128 block sizes used by quant layout
#define TCA_BYTES (128 * BK * 2)     // 32768
#define TCB_BYTES (256 * BK * 2)     // 65536

// ---------------- device scratch (static, no allocs) ----------------
__device__ unsigned int g_amax[2];
__device__ float g_scale[4];                 // ls, rs, 1/(ls*rs)
// bf16 path operands (32MB each)
__device__ __align__(1024) uint16_t g_qa[(size_t)DIM * DIM];
__device__ __align__(1024) uint16_t g_qb[(size_t)DIM * DIM];
// int8 fallback operands
__device__ __align__(1024) int8_t g_qa8[(size_t)DIM * DIM];
__device__ __align__(1024) int8_t g_qb8[(size_t)DIM * DIM];

// ---------------- helpers ----------------
#define SWZ(o) ((o) ^ (((o) >> 3) & 0x70))

__device__ __forceinline__ uint32_t smem_u32(const void* p) {
    uint32_t a;
    asm("{ .reg .u64 t; cvta.to.shared.u64 t, %1; cvt.u32.u64 %0, t; }" : "=r"(a) : "l"(p));
    return a;
}
__device__ __forceinline__ void mbar_init(uint32_t a, uint32_t cnt) {
    asm volatile("mbarrier.init.shared.b64 [%0], %1;" :: "r"(a), "r"(cnt) : "memory");
}
__device__ __forceinline__ void mbar_expect_tx(uint32_t a, uint32_t bytes) {
    asm volatile("mbarrier.arrive.expect_tx.shared.b64 _, [%0], %1;" :: "r"(a), "r"(bytes) : "memory");
}
__device__ __forceinline__ void mbar_arrive(uint32_t a) {
    asm volatile("mbarrier.arrive.shared.b64 _, [%0];" :: "r"(a) : "memory");
}
__device__ __forceinline__ void mbar_wait(uint32_t a, uint32_t parity) {
    asm volatile(
        "{\n\t.reg .pred P;\n\t"
        "WL_%=:\n\t"
        "mbarrier.try_wait.parity.acquire.cta.shared::cta.b64 P, [%0], %1, 0x989680;\n\t"
        "@P bra.uni WD_%=;\n\t"
        "bra.uni WL_%=;\n\t"
        "WD_%=:\n\t}"
        :: "r"(a), "r"(parity) : "memory");
}
__device__ __forceinline__ void bulk_g2s(uint32_t dst, const void* src, uint32_t bytes, uint32_t mbar) {
    asm volatile("cp.async.bulk.shared::cluster.global.mbarrier::complete_tx::bytes [%0], [%1], %2, [%3];"
                 :: "r"(dst), "l"(src), "r"(bytes), "r"(mbar) : "memory");
}
__device__ __forceinline__ void bulk_g2s_mc(uint32_t dst, const void* src, uint32_t bytes,
                                            uint32_t mbar, uint16_t mask) {
    asm volatile("cp.async.bulk.shared::cluster.global.mbarrier::complete_tx::bytes.multicast::cluster "
                 "[%0], [%1], %2, [%3], %4;"
                 :: "r"(dst), "l"(src), "r"(bytes), "r"(mbar), "h"(mask) : "memory");
}
__device__ __forceinline__ void ldsm_x4(uint32_t* r, uint32_t addr) {
    asm volatile("ldmatrix.sync.aligned.m8n8.x4.shared.b16 {%0,%1,%2,%3}, [%4];"
                 : "=r"(r[0]), "=r"(r[1]), "=r"(r[2]), "=r"(r[3]) : "r"(addr));
}
__device__ __forceinline__ void mma_s8(int* d, const uint32_t* a, uint32_t b0, uint32_t b1) {
    asm volatile(
        "mma.sync.aligned.m16n8k32.row.col.s32.s8.s8.s32 "
        "{%0,%1,%2,%3}, {%4,%5,%6,%7}, {%8,%9}, {%0,%1,%2,%3};"
        : "+r"(d[0]), "+r"(d[1]), "+r"(d[2]), "+r"(d[3])
        : "r"(a[0]), "r"(a[1]), "r"(a[2]), "r"(a[3]), "r"(b0), "r"(b1));
}

// ---------------- pre-pass kernels ----------------
__global__ void k_reset() {
    if (threadIdx.x < 2) g_amax[threadIdx.x] = 0u;
}

// fused: blockIdx.y selects tensor/slot
__global__ void k_amax2(const float4* __restrict__ a, const float4* __restrict__ b) {
    const float4* x = blockIdx.y ? b : a;
    float m = 0.0f;
    size_t stride = (size_t)gridDim.x * blockDim.x;
    size_t n4 = ((size_t)DIM * DIM) / 4;
    for (size_t j = blockIdx.x * (size_t)blockDim.x + threadIdx.x; j < n4; j += stride) {
        float4 v = x[j];
        m = fmaxf(m, fmaxf(fmaxf(fabsf(v.x), fabsf(v.y)), fmaxf(fabsf(v.z), fabsf(v.w))));
    }
#pragma unroll
    for (int o = 16; o; o >>= 1) m = fmaxf(m, __shfl_xor_sync(0xffffffffu, m, o));
    if ((threadIdx.x & 31) == 0) atomicMax(&g_amax[blockIdx.y], __float_as_uint(m));
}

__global__ void k_scale() {
    float ls = 127.0f / fmaxf(__uint_as_float(g_amax[0]), 1e-12f);
    float rs = 127.0f / fmaxf(__uint_as_float(g_amax[1]), 1e-12f);
    g_scale[0] = ls;
    g_scale[1] = rs;
    g_scale[2] = 1.0f / (ls * rs);
}

__device__ __forceinline__ float q8f(float v, float s) {
    float f = rintf(v * s);                      // round-half-even == jnp.round
    return fminf(fmaxf(f, -127.0f), 127.0f);     // exact small integer
}
__device__ __forceinline__ uint16_t bf16_bits(float f) {
    return (uint16_t)__bfloat16_as_ushort(__float2bfloat16_rn(f));
}

// ======== bf16 quant pre-passes (tcgen05 path) ========
// A: [mb128][k64] 16KB blocks: rows r(128) x 64 bf16 (128B rows, SW128)
__global__ void k_quant_a_bf(const float* __restrict__ lhs) {
    const float ls = g_scale[0];
    size_t t = blockIdx.x * (size_t)blockDim.x + threadIdx.x;   // 2M threads, 8 elems each
    size_t e = t * 8;
    uint32_t row = (uint32_t)(e >> 12);
    uint32_t col = (uint32_t)(e & 4095);
    uint32_t mb = row >> 7, r = row & 127;
    uint32_t kb = col >> 7, kl = col & 127;
    uint32_t k64 = kl >> 6, c = kl & 63;
    const float4* src = (const float4*)(lhs + e);
    float4 v0 = src[0], v1 = src[1];
    union { uint16_t q[8]; int4 p; } u;
    u.q[0] = bf16_bits(q8f(v0.x, ls)); u.q[1] = bf16_bits(q8f(v0.y, ls));
    u.q[2] = bf16_bits(q8f(v0.z, ls)); u.q[3] = bf16_bits(q8f(v0.w, ls));
    u.q[4] = bf16_bits(q8f(v1.x, ls)); u.q[5] = bf16_bits(q8f(v1.y, ls));
    u.q[6] = bf16_bits(q8f(v1.z, ls)); u.q[7] = bf16_bits(q8f(v1.w, ls));
    size_t off = (size_t)(mb * NKB + kb) * TCA_BYTES + k64 * 16384 + SWZ(r * 128 + c * 2);
    *(int4*)((char*)g_qa + off) = u.p;
}

// B: [nb256][k64] 32KB blocks: rows n(256) x 64 bf16 (SW128)
__global__ void k_quant_b_bf(const float* __restrict__ rhs) {
    __shared__ __align__(16) uint16_t s[32][136];   // [n][k] bf16, padded
    const float rsc = g_scale[1];
    const uint32_t n0 = blockIdx.x * 32;
    const uint32_t kb = blockIdx.y;
    const uint32_t k0 = kb * 128;
    const int tid = threadIdx.x;           // 256 threads
    const int wp = tid >> 5, lane = tid & 31;
#pragma unroll
    for (int kk = wp; kk < 128; kk += 8) {
        float v = rhs[(size_t)(k0 + kk) * DIM + n0 + lane];
        s[lane][kk] = bf16_bits(q8f(v, rsc));
    }
    __syncthreads();
    const uint32_t nb = n0 >> 8;
    const size_t tile = (size_t)(nb * NKB + kb) * TCB_BYTES;
#pragma unroll
    for (int it = 0; it < 2; it++) {
        int idx = tid + it * 256;          // 0..511
        int n = idx >> 4;                  // 0..31
        int c16 = idx & 15;                // 16B chunk along k
        int4 v = *(int4*)&s[n][c16 * 8];
        uint32_t k64 = c16 >> 3, cb = (c16 & 7) * 16;
        uint32_t nrow = (n0 & 255) + n;
        *(int4*)((char*)g_qb + tile + k64 * 32768 + SWZ(nrow * 128 + cb)) = v;
    }
}

// ======== int8 quant pre-passes (fallback path) ========
__global__ void k_quant_a8(const float* __restrict__ lhs) {
    const float ls = g_scale[0];
    size_t t = blockIdx.x * (size_t)blockDim.x + threadIdx.x;
    size_t e = t * 16;
    uint32_t row = (uint32_t)(e >> 12);
    uint32_t col = (uint32_t)(e & 4095);
    uint32_t mb = row >> 7, r = row & 127;
    uint32_t kb = col >> 7, c = col & 127;
    const float4* src = (const float4*)(lhs + e);
    int4 packed;
    int8_t* q = (int8_t*)&packed;
#pragma unroll
    for (int i = 0; i < 4; i++) {
        float4 v = src[i];
        q[i * 4 + 0] = (int8_t)q8f(v.x, ls);
        q[i * 4 + 1] = (int8_t)q8f(v.y, ls);
        q[i * 4 + 2] = (int8_t)q8f(v.z, ls);
        q[i * 4 + 3] = (int8_t)q8f(v.w, ls);
    }
    size_t tile = (size_t)(mb * NKB + kb) * (size_t)A_BYTES;
    *(int4*)(g_qa8 + tile + SWZ(r * 128 + c)) = packed;
}

__global__ void k_quant_b8(const float* __restrict__ rhs) {
    __shared__ int8_t s[32 * 144];
    const float rsc = g_scale[1];
    const uint32_t n0 = blockIdx.x * 32;
    const uint32_t kb = blockIdx.y;
    const uint32_t k0 = kb * 128;
    const int tid = threadIdx.x;
    const int wp = tid >> 5, lane = tid & 31;
#pragma unroll
    for (int kk = wp; kk < 128; kk += 8) {
        float v = rhs[(size_t)(k0 + kk) * DIM + n0 + lane];
        s[lane * 144 + kk] = (int8_t)q8f(v, rsc);
    }
    __syncthreads();
    const uint32_t n = tid >> 3, ch = tid & 7;
    int4 v = *(int4*)&s[n * 144 + ch * 16];
    const uint32_t nb = n0 >> 7;
    const uint32_t nloc = (n0 & 127) + n;
    size_t tile = (size_t)(nb * NKB + kb) * (size_t)B_BYTES;
    *(int4*)(g_qb8 + tile + SWZ(nloc * 128 + ch * 16)) = v;
}

// ===== tcgen05 bf16 GEMM, 256x256 tile, cluster (2,2,1) operand multicast =====
__global__ void __launch_bounds__(256, 1) __cluster_dims__(2, 2, 1)
k_gemm_tc(float* __restrict__ out) {
#if HAS_TCGEN05
    extern __shared__ char smem[];
    const uint32_t sb = smem_u32(smem);
    const uint32_t FULLB = sb;           // 3 x 8B
    const uint32_t EMPTB = sb + 64;      // 3 x 8B
    const uint32_t DONEB = sb + 128;
    const uint32_t TMEMP = sb + 192;
    const uint32_t TILES = (sb + 1024 + 1023) & ~1023u;   // 1024-aligned for SW128
    const int tid = threadIdx.x, wid = tid >> 5, lane = tid & 31;
    const int nb = blockIdx.x, mb = blockIdx.y;
    const int cx = nb & 1, cy = mb & 1;               // cluster-local coords
    const int rank = cy * 2 + cx;

    if (wid == 0) {
        asm volatile("tcgen05.alloc.cta_group::1.sync.aligned.shared::cta.b32 [%0], %1;"
                     :: "r"(TMEMP), "r"(512) : "memory");
        asm volatile("tcgen05.relinquish_alloc_permit.cta_group::1.sync.aligned;");
    }
    if (tid == 0) {
        for (int s = 0; s < TC_NSTAGE; s++) {
            mbar_init(FULLB + 8 * s, 1);     // 1 arrive (local expect_tx), tx-gated
            mbar_init(EMPTB + 8 * s, 3);     // commits from self + x-neighbor + y-neighbor
        }
        mbar_init(DONEB, 1);
    }
    __syncthreads();
    // cluster-wide: all mbarriers visible before any multicast lands
    asm volatile("barrier.cluster.arrive.aligned;" ::: "memory");
    asm volatile("barrier.cluster.wait.aligned;" ::: "memory");

    uint32_t tmem;
    asm volatile("ld.shared.b32 %0, [%1];" : "=r"(tmem) : "r"(TMEMP));

    // f16-kind idesc: dtype=F32(1<<4), atype=BF16(1<<7), btype=BF16(1<<10), N/8@17, M/16@24
    const uint32_t idesc =
        (1u << 4) | (1u << 7) | (1u << 10) | ((TC_BN / 8) << 17) | ((128 / 16) << 24);

    if (tid == 0) {
        // this CTA fetches: A half 'cx' of its mb row-pair, B half 'cy' of its nb block
        const char* asrc = (const char*)g_qa + (size_t)(2 * mb + cx) * NK64 * A64_BYTES;
        const char* bsrc = (const char*)g_qb + (size_t)nb * NK64 * B64_BYTES + (size_t)cy * 16384;
        const uint32_t adst = (uint32_t)cx * A64_BYTES;
        const uint32_t bdst = 2 * A64_BYTES + (uint32_t)cy * 16384;
        const uint16_t maskA = (uint16_t)((1u << rank) | (1u << (rank ^ 1)));  // x-pair
        const uint16_t maskB = (uint16_t)((1u << rank) | (1u << (rank ^ 2)));  // y-pair
        const uint16_t maskC = (uint16_t)(maskA | maskB);

        uint32_t fpar[TC_NSTAGE] = {0, 0, 0}, epar[TC_NSTAGE] = {0, 0, 0};
        // prologue: stages 0,1
#pragma unroll
        for (int p = 0; p < 2; p++) {
            uint32_t st = TILES + p * TC_STAGE_BYTES;
            mbar_expect_tx(FULLB + 8 * p, TC_STAGE_BYTES);
            bulk_g2s_mc(st + adst, asrc + (size_t)p * A64_BYTES, A64_BYTES, FULLB + 8 * p, maskA);
            bulk_g2s_mc(st + bdst, bsrc + (size_t)p * B64_BYTES, A64_BYTES, FULLB + 8 * p, maskB);
        }
        int s = 0;
        for (int kb = 0; kb < NK64; kb++) {
            int rb = kb + 2;
            if (rb < NK64) {
                int s2 = rb - (rb / 3) * 3;
                if (rb >= 3) { mbar_wait(EMPTB + 8 * s2, epar[s2]); epar[s2] ^= 1; }
                uint32_t st2 = TILES + s2 * TC_STAGE_BYTES;
                mbar_expect_tx(FULLB + 8 * s2, TC_STAGE_BYTES);
                bulk_g2s_mc(st2 + adst, asrc + (size_t)rb * A64_BYTES, A64_BYTES, FULLB + 8 * s2, maskA);
                bulk_g2s_mc(st2 + bdst, bsrc + (size_t)rb * B64_BYTES, A64_BYTES, FULLB + 8 * s2, maskB);
            }
            mbar_wait(FULLB + 8 * s, fpar[s]); fpar[s] ^= 1;
            uint32_t st = TILES + s * TC_STAGE_BYTES;
            uint64_t base = ((uint64_t)2 << 61) | ((uint64_t)1 << 46) | ((uint64_t)64 << 32) |
                            ((uint64_t)1 << 16);
            uint64_t ad0 = base | (uint64_t)((st >> 4) & 0x3FFF);
            uint64_t ad1 = base | (uint64_t)(((st + A64_BYTES) >> 4) & 0x3FFF);
            uint64_t bd  = base | (uint64_t)(((st + 2 * A64_BYTES) >> 4) & 0x3FFF);
#pragma unroll
            for (int j = 0; j < 4; j++) {          // four K=16 steps per k64
                uint32_t en = (uint32_t)((kb | j) != 0);
                asm volatile(
                    "{\n\t.reg .pred p;\n\t"
                    "setp.ne.u32 p, %4, 0;\n\t"
                    "tcgen05.mma.cta_group::1.kind::f16 [%0], %1, %2, %3, p;\n\t}"
                    :: "r"(tmem), "l"(ad0 + j * 2), "l"(bd + j * 2), "r"(idesc), "r"(en)
                    : "memory");
                asm volatile(
                    "{\n\t.reg .pred p;\n\t"
                    "setp.ne.u32 p, %4, 0;\n\t"
                    "tcgen05.mma.cta_group::1.kind::f16 [%0], %1, %2, %3, p;\n\t}"
                    :: "r"(tmem + 256), "l"(ad1 + j * 2), "l"(bd + j * 2), "r"(idesc), "r"(en)
                    : "memory");
            }
            // release stage s in all CTAs whose smem we (or our pairs) wrote
            asm volatile(
                "tcgen05.commit.cta_group::1.mbarrier::arrive::one.shared::cluster.multicast::cluster.b64 [%0], %1;"
                :: "r"(EMPTB + 8 * s), "h"(maskC) : "memory");
            s++; if (s == TC_NSTAGE) s = 0;
        }
        asm volatile("tcgen05.commit.cta_group::1.mbarrier::arrive::one.shared::cluster.b64 [%0];"
                     :: "r"(DONEB) : "memory");
    }

    mbar_wait(DONEB, 0);
    asm volatile("tcgen05.fence::after_thread_sync;" ::: "memory");

    // epilogue: WG0 reads D0 (cols 0-255, M rows 0-127); WG1 reads D1 (cols 256-511, rows 128-255)
    const float inv = g_scale[2];
    const int wg = tid >> 7;                 // 0 or 1
    const uint32_t dbase = tmem + wg * 256;
    const size_t row = (size_t)mb * TC_BM + wg * 128 + (wid & 3) * 32 + lane;
    float* orow = out + row * DIM + (size_t)nb * TC_BN;
#pragma unroll 1
    for (int c8 = 0; c8 < TC_BN / 32; c8++) {
        uint32_t r[32];
        asm volatile(
            "tcgen05.ld.sync.aligned.32x32b.x32.b32 "
            "{%0, %1, %2, %3, %4, %5, %6, %7, "
            " %8, %9, %10, %11, %12, %13, %14, %15, "
            " %16, %17, %18, %19, %20, %21, %22, %23, "
            " %24, %25, %26, %27, %28, %29, %30, %31}, [%32];"
            : "=r"(r[0]), "=r"(r[1]), "=r"(r[2]), "=r"(r[3]),
              "=r"(r[4]), "=r"(r[5]), "=r"(r[6]), "=r"(r[7]),
              "=r"(r[8]), "=r"(r[9]), "=r"(r[10]), "=r"(r[11]),
              "=r"(r[12]), "=r"(r[13]), "=r"(r[14]), "=r"(r[15]),
              "=r"(r[16]), "=r"(r[17]), "=r"(r[18]), "=r"(r[19]),
              "=r"(r[20]), "=r"(r[21]), "=r"(r[22]), "=r"(r[23]),
              "=r"(r[24]), "=r"(r[25]), "=r"(r[26]), "=r"(r[27]),
              "=r"(r[28]), "=r"(r[29]), "=r"(r[30]), "=r"(r[31])
            : "r"(dbase + c8 * 32));
        asm volatile("tcgen05.wait::ld.sync.aligned;" ::: "memory");
#pragma unroll
        for (int i = 0; i < 32; i += 4) {
            float4 v;
            v.x = __uint_as_float(r[i + 0]) * inv;
            v.y = __uint_as_float(r[i + 1]) * inv;
            v.z = __uint_as_float(r[i + 2]) * inv;
            v.w = __uint_as_float(r[i + 3]) * inv;
            *(float4*)(orow + c8 * 32 + i) = v;
        }
    }
    __syncthreads();
    if (wid == 0) {
        asm volatile("tcgen05.dealloc.cta_group::1.sync.aligned.b32 %0, %1;" :: "r"(tmem), "r"(512));
    }
    // no CTA may exit while a peer multicast targeting its smem could be in flight
    asm volatile("barrier.cluster.arrive.aligned;" ::: "memory");
    asm volatile("barrier.cluster.wait.aligned;" ::: "memory");
#endif
}

// ================= fallback path (generic pass only) — known-good R2 =================
__global__ void __launch_bounds__(256, 1) k_gemm_mma(float* __restrict__ out) {
#if !HAS_TCGEN05
    extern __shared__ char smem[];
    const uint32_t sb = smem_u32(smem);
    const uint32_t FULLB = sb;
    const uint32_t EMPTB = sb + 64;
    const uint32_t TILES = (sb + 1024 + 1023) & ~1023u;
    const int tid = threadIdx.x, wid = tid >> 5, lane = tid & 31;
    const int nb = blockIdx.x, mb = blockIdx.y;
    const int warp_m = wid & 1, warp_n = wid >> 1;

    if (tid == 0) {
        for (int s = 0; s < STAGES; s++) {
            mbar_init(FULLB + 8 * s, 1);
            mbar_init(EMPTB + 8 * s, 8);
        }
    }
    __syncthreads();

    const int8_t* abase = g_qa8 + (size_t)mb * NKB * A_BYTES;
    const int8_t* bbase = g_qb8 + (size_t)nb * NKB * B_BYTES;

    if (tid == 0) {
#pragma unroll
        for (int p = 0; p < STAGES - 1; p++) {
            uint32_t st = TILES + p * STAGE_BYTES;
            mbar_expect_tx(FULLB + 8 * p, STAGE_BYTES);
            bulk_g2s(st, abase + (size_t)p * A_BYTES, A_BYTES, FULLB + 8 * p);
            bulk_g2s(st + A_BYTES, bbase + (size_t)p * B_BYTES, B_BYTES, FULLB + 8 * p);
        }
    }

    uint32_t preA[4];
#pragma unroll
    for (int mt = 0; mt < 4; mt++) {
        uint32_t row = warp_m * 64 + mt * 16 + (lane & 15);
        preA[mt] = (row * 128) ^ ((row & 7) << 4) ^ ((uint32_t)(lane >> 4) * 16);
    }
    uint32_t preB[2];
#pragma unroll
    for (int np = 0; np < 2; np++) {
        uint32_t n = warp_n * 32 + np * 16 + (lane & 7) + ((lane >> 4) << 3);
        preB[np] = (n * 128) ^ ((n & 7) << 4) ^ ((((uint32_t)lane >> 3) & 1) * 16);
    }

    int acc[4][4][4];
#pragma unroll
    for (int i = 0; i < 4; i++)
#pragma unroll
        for (int j = 0; j < 4; j++)
#pragma unroll
            for (int k = 0; k < 4; k++) acc[i][j][k] = 0;

    for (int kb = 0; kb < NKB; kb++) {
        int s = kb & (STAGES - 1);
        int rb = kb + STAGES - 1;
        if (tid == 0 && rb < NKB) {
            int rs_ = rb & (STAGES - 1);
            if (rb >= STAGES) mbar_wait(EMPTB + 8 * rs_, ((rb / STAGES) - 1) & 1);
            uint32_t st = TILES + rs_ * STAGE_BYTES;
            mbar_expect_tx(FULLB + 8 * rs_, STAGE_BYTES);
            bulk_g2s(st, abase + (size_t)rb * A_BYTES, A_BYTES, FULLB + 8 * rs_);
            bulk_g2s(st + A_BYTES, bbase + (size_t)rb * B_BYTES, B_BYTES, FULLB + 8 * rs_);
        }
        mbar_wait(FULLB + 8 * s, (kb / STAGES) & 1);
        uint32_t As = TILES + s * STAGE_BYTES;
        uint32_t Bs = As + A_BYTES;
#pragma unroll
        for (int c = 0; c < 4; c++) {
            uint32_t koff = (uint32_t)c << 5;
            uint32_t a[4][4], b[2][4];
#pragma unroll
            for (int mt = 0; mt < 4; mt++) ldsm_x4(a[mt], As + (preA[mt] ^ koff));
#pragma unroll
            for (int np = 0; np < 2; np++) ldsm_x4(b[np], Bs + (preB[np] ^ koff));
#pragma unroll
            for (int mt = 0; mt < 4; mt++) {
#pragma unroll
                for (int nt = 0; nt < 4; nt++) {
                    const uint32_t* bp = b[nt >> 1];
                    mma_s8(acc[mt][nt], a[mt], bp[(nt & 1) * 2], bp[(nt & 1) * 2 + 1]);
                }
            }
        }
        if (lane == 0) mbar_arrive(EMPTB + 8 * s);
    }

    const float inv = g_scale[2];
    const uint32_t r0 = mb * BM + warp_m * 64 + (lane >> 2);
    const uint32_t c0 = nb * BN + warp_n * 32 + (lane & 3) * 2;
#pragma unroll
    for (int mt = 0; mt < 4; mt++) {
#pragma unroll
        for (int nt = 0; nt < 4; nt++) {
            float2 v0, v1;
            v0.x = __int2float_rn(acc[mt][nt][0]) * inv;
            v0.y = __int2float_rn(acc[mt][nt][1]) * inv;
            v1.x = __int2float_rn(acc[mt][nt][2]) * inv;
            v1.y = __int2float_rn(acc[mt][nt][3]) * inv;
            size_t base = (size_t)(r0 + mt * 16) * DIM + c0 + nt * 8;
            *(float2*)(out + base) = v0;
            *(float2*)(out + base + 8 * DIM) = v1;
        }
    }
#endif
}

__device__ int g_has_tc_dev = HAS_TCGEN05;   // 1 in specific pass, 0 in generic

// ---------------- launch ----------------
extern "C" void kernel_launch(void* const* d_in, const int* in_sizes, int n_in,
                              void* d_out, int out_size) {
    (void)in_sizes; (void)n_in; (void)out_size;
    const float* lhs = (const float*)d_in[0];
    const float* rhs = (const float*)d_in[1];
    float* out = (float*)d_out;

    static int has_tc = -1;
    if (has_tc < 0) {
        int v = 0;
        cudaMemcpyFromSymbol(&v, g_has_tc_dev, sizeof(int));   // pre-capture call only
        has_tc = v;
        cudaFuncSetAttribute(k_gemm_mma, cudaFuncAttributeMaxDynamicSharedMemorySize, GEMM_SMEM);
        cudaFuncSetAttribute(k_gemm_tc, cudaFuncAttributeMaxDynamicSharedMemorySize, TC_SMEM);
    }

    k_reset<<<1, 32>>>();
    dim3 ga(1024, 2);
    k_amax2<<<ga, 256>>>((const float4*)lhs, (const float4*)rhs);
    k_scale<<<1, 1>>>();

    if (has_tc) {
        k_quant_a_bf<<<8192, 256>>>(lhs);
        dim3 gb(DIM / 32, DIM / BK);
        k_quant_b_bf<<<gb, 256>>>(rhs);
        dim3 gt(DIM / TC_BN, DIM / TC_BM);
        k_gemm_tc<<<gt, 256, TC_SMEM>>>(out);
    } else {
        k_quant_a8<<<4096, 256>>>(lhs);
        dim3 gb(DIM / 32, DIM / BK);
        k_quant_b8<<<gb, 256>>>(rhs);
        dim3 gg(DIM / BN, DIM / BM);
        k_gemm_mma<<<gg, 256, GEMM_SMEM>>>(out);
    }
}

// round 10
// speedup vs baseline: 1.2724x; 1.2724x over previous
#include <cuda_runtime.h>
#include <cuda_bf16.h>
#include <cstdint>

// ---- arch capability: tcgen05 legal only in arch/family-specific device pass ----
#if defined(__CUDA_ARCH__) && (defined(__CUDA_ARCH_SPECIFIC__) || defined(__CUDA_ARCH_FAMILY_SPECIFIC__))
#define HAS_TCGEN05 1
#else
#define HAS_TCGEN05 0
#endif

#define DIM 4096
#define NKB 32              // DIM / 128 (quant tile granularity)
#define BK 128

// ---- fallback (mma.sync int8) tiling — known-good R2 path ----
#define BM 128
#define BN 128
#define A_BYTES (BM * BK)
#define B_BYTES (BN * BK)
#define STAGES 4
#define STAGE_BYTES (A_BYTES + B_BYTES)
#define GEMM_SMEM (2048 + STAGES * STAGE_BYTES)

// ---- tcgen05 bf16 tiling: 256x256 CTA tile, BK=64, 3 stages ----
#define TC_BM 256
#define TC_BN 256
#define NK64 64                          // DIM / 64
#define A64_BYTES (128 * 64 * 2)         // 16384 per M-half per k64
#define B64_BYTES (256 * 64 * 2)         // 32768 per k64
#define TC_STAGE_BYTES (2 * A64_BYTES + B64_BYTES)   // 65536
#define TC_NSTAGE 3
#define TC_SMEM (2048 + TC_NSTAGE * TC_STAGE_BYTES)  // 198656

// legacy per-128 block sizes used by quant layout
#define TCA_BYTES (128 * BK * 2)     // 32768
#define TCB_BYTES (256 * BK * 2)     // 65536

// ---------------- device scratch (static, no allocs) ----------------
__device__ unsigned int g_amax[2];
// bf16 path operands (32MB each)
__device__ __align__(1024) uint16_t g_qa[(size_t)DIM * DIM];
__device__ __align__(1024) uint16_t g_qb[(size_t)DIM * DIM];
// int8 fallback operands
__device__ __align__(1024) int8_t g_qa8[(size_t)DIM * DIM];
__device__ __align__(1024) int8_t g_qb8[(size_t)DIM * DIM];

// ---------------- helpers ----------------
#define SWZ(o) ((o) ^ (((o) >> 3) & 0x70))

__device__ __forceinline__ float load_scale(int slot) {
    return 127.0f / fmaxf(__uint_as_float(g_amax[slot]), 1e-12f);
}
__device__ __forceinline__ float load_inv() {
    float ls = load_scale(0), rs = load_scale(1);
    return 1.0f / (ls * rs);
}

__device__ __forceinline__ uint32_t smem_u32(const void* p) {
    uint32_t a;
    asm("{ .reg .u64 t; cvta.to.shared.u64 t, %1; cvt.u32.u64 %0, t; }" : "=r"(a) : "l"(p));
    return a;
}
__device__ __forceinline__ void mbar_init(uint32_t a, uint32_t cnt) {
    asm volatile("mbarrier.init.shared.b64 [%0], %1;" :: "r"(a), "r"(cnt) : "memory");
}
__device__ __forceinline__ void mbar_expect_tx(uint32_t a, uint32_t bytes) {
    asm volatile("mbarrier.arrive.expect_tx.shared.b64 _, [%0], %1;" :: "r"(a), "r"(bytes) : "memory");
}
__device__ __forceinline__ void mbar_arrive(uint32_t a) {
    asm volatile("mbarrier.arrive.shared.b64 _, [%0];" :: "r"(a) : "memory");
}
__device__ __forceinline__ void mbar_wait(uint32_t a, uint32_t parity) {
    asm volatile(
        "{\n\t.reg .pred P;\n\t"
        "WL_%=:\n\t"
        "mbarrier.try_wait.parity.acquire.cta.shared::cta.b64 P, [%0], %1, 0x989680;\n\t"
        "@P bra.uni WD_%=;\n\t"
        "bra.uni WL_%=;\n\t"
        "WD_%=:\n\t}"
        :: "r"(a), "r"(parity) : "memory");
}
__device__ __forceinline__ void bulk_g2s(uint32_t dst, const void* src, uint32_t bytes, uint32_t mbar) {
    asm volatile("cp.async.bulk.shared::cluster.global.mbarrier::complete_tx::bytes [%0], [%1], %2, [%3];"
                 :: "r"(dst), "l"(src), "r"(bytes), "r"(mbar) : "memory");
}
__device__ __forceinline__ void ldsm_x4(uint32_t* r, uint32_t addr) {
    asm volatile("ldmatrix.sync.aligned.m8n8.x4.shared.b16 {%0,%1,%2,%3}, [%4];"
                 : "=r"(r[0]), "=r"(r[1]), "=r"(r[2]), "=r"(r[3]) : "r"(addr));
}
__device__ __forceinline__ void mma_s8(int* d, const uint32_t* a, uint32_t b0, uint32_t b1) {
    asm volatile(
        "mma.sync.aligned.m16n8k32.row.col.s32.s8.s8.s32 "
        "{%0,%1,%2,%3}, {%4,%5,%6,%7}, {%8,%9}, {%0,%1,%2,%3};"
        : "+r"(d[0]), "+r"(d[1]), "+r"(d[2]), "+r"(d[3])
        : "r"(a[0]), "r"(a[1]), "r"(a[2]), "r"(a[3]), "r"(b0), "r"(b1));
}

// ---------------- pre-pass kernels ----------------
// fused: blockIdx.y selects tensor/slot
__global__ void k_amax2(const float4* __restrict__ a, const float4* __restrict__ b) {
    const float4* x = blockIdx.y ? b : a;
    float m = 0.0f;
    size_t stride = (size_t)gridDim.x * blockDim.x;
    size_t n4 = ((size_t)DIM * DIM) / 4;
    for (size_t j = blockIdx.x * (size_t)blockDim.x + threadIdx.x; j < n4; j += stride) {
        float4 v = x[j];
        m = fmaxf(m, fmaxf(fmaxf(fabsf(v.x), fabsf(v.y)), fmaxf(fabsf(v.z), fabsf(v.w))));
    }
#pragma unroll
    for (int o = 16; o; o >>= 1) m = fmaxf(m, __shfl_xor_sync(0xffffffffu, m, o));
    if ((threadIdx.x & 31) == 0) atomicMax(&g_amax[blockIdx.y], __float_as_uint(m));
}

__device__ __forceinline__ float q8f(float v, float s) {
    float f = rintf(v * s);                      // round-half-even == jnp.round
    return fminf(fmaxf(f, -127.0f), 127.0f);     // exact small integer
}
__device__ __forceinline__ uint16_t bf16_bits(float f) {
    return (uint16_t)__bfloat16_as_ushort(__float2bfloat16_rn(f));
}

// ======== bf16 quant pre-passes (tcgen05 path) ========
// A: [mb128][k64] 16KB blocks: rows r(128) x 64 bf16 (128B rows, SW128)
__global__ void k_quant_a_bf(const float* __restrict__ lhs) {
    const float ls = load_scale(0);
    size_t t = blockIdx.x * (size_t)blockDim.x + threadIdx.x;   // 2M threads, 8 elems each
    size_t e = t * 8;
    uint32_t row = (uint32_t)(e >> 12);
    uint32_t col = (uint32_t)(e & 4095);
    uint32_t mb = row >> 7, r = row & 127;
    uint32_t kb = col >> 7, kl = col & 127;
    uint32_t k64 = kl >> 6, c = kl & 63;
    const float4* src = (const float4*)(lhs + e);
    float4 v0 = src[0], v1 = src[1];
    union { uint16_t q[8]; int4 p; } u;
    u.q[0] = bf16_bits(q8f(v0.x, ls)); u.q[1] = bf16_bits(q8f(v0.y, ls));
    u.q[2] = bf16_bits(q8f(v0.z, ls)); u.q[3] = bf16_bits(q8f(v0.w, ls));
    u.q[4] = bf16_bits(q8f(v1.x, ls)); u.q[5] = bf16_bits(q8f(v1.y, ls));
    u.q[6] = bf16_bits(q8f(v1.z, ls)); u.q[7] = bf16_bits(q8f(v1.w, ls));
    size_t off = (size_t)(mb * NKB + kb) * TCA_BYTES + k64 * 16384 + SWZ(r * 128 + c * 2);
    *(int4*)((char*)g_qa + off) = u.p;
}

// B: [nb256][k64] 32KB blocks: rows n(256) x 64 bf16 (SW128)
__global__ void k_quant_b_bf(const float* __restrict__ rhs) {
    __shared__ __align__(16) uint16_t s[32][136];   // [n][k] bf16, padded
    const float rsc = load_scale(1);
    const uint32_t n0 = blockIdx.x * 32;
    const uint32_t kb = blockIdx.y;
    const uint32_t k0 = kb * 128;
    const int tid = threadIdx.x;           // 256 threads
    const int wp = tid >> 5, lane = tid & 31;
#pragma unroll
    for (int kk = wp; kk < 128; kk += 8) {
        float v = rhs[(size_t)(k0 + kk) * DIM + n0 + lane];
        s[lane][kk] = bf16_bits(q8f(v, rsc));
    }
    __syncthreads();
    const uint32_t nb = n0 >> 8;
    const size_t tile = (size_t)(nb * NKB + kb) * TCB_BYTES;
#pragma unroll
    for (int it = 0; it < 2; it++) {
        int idx = tid + it * 256;          // 0..511
        int n = idx >> 4;                  // 0..31
        int c16 = idx & 15;                // 16B chunk along k
        int4 v = *(int4*)&s[n][c16 * 8];
        uint32_t k64 = c16 >> 3, cb = (c16 & 7) * 16;
        uint32_t nrow = (n0 & 255) + n;
        *(int4*)((char*)g_qb + tile + k64 * 32768 + SWZ(nrow * 128 + cb)) = v;
    }
}

// ======== int8 quant pre-passes (fallback path) ========
__global__ void k_quant_a8(const float* __restrict__ lhs) {
    const float ls = load_scale(0);
    size_t t = blockIdx.x * (size_t)blockDim.x + threadIdx.x;
    size_t e = t * 16;
    uint32_t row = (uint32_t)(e >> 12);
    uint32_t col = (uint32_t)(e & 4095);
    uint32_t mb = row >> 7, r = row & 127;
    uint32_t kb = col >> 7, c = col & 127;
    const float4* src = (const float4*)(lhs + e);
    int4 packed;
    int8_t* q = (int8_t*)&packed;
#pragma unroll
    for (int i = 0; i < 4; i++) {
        float4 v = src[i];
        q[i * 4 + 0] = (int8_t)q8f(v.x, ls);
        q[i * 4 + 1] = (int8_t)q8f(v.y, ls);
        q[i * 4 + 2] = (int8_t)q8f(v.z, ls);
        q[i * 4 + 3] = (int8_t)q8f(v.w, ls);
    }
    size_t tile = (size_t)(mb * NKB + kb) * (size_t)A_BYTES;
    *(int4*)(g_qa8 + tile + SWZ(r * 128 + c)) = packed;
}

__global__ void k_quant_b8(const float* __restrict__ rhs) {
    __shared__ int8_t s[32 * 144];
    const float rsc = load_scale(1);
    const uint32_t n0 = blockIdx.x * 32;
    const uint32_t kb = blockIdx.y;
    const uint32_t k0 = kb * 128;
    const int tid = threadIdx.x;
    const int wp = tid >> 5, lane = tid & 31;
#pragma unroll
    for (int kk = wp; kk < 128; kk += 8) {
        float v = rhs[(size_t)(k0 + kk) * DIM + n0 + lane];
        s[lane * 144 + kk] = (int8_t)q8f(v, rsc);
    }
    __syncthreads();
    const uint32_t n = tid >> 3, ch = tid & 7;
    int4 v = *(int4*)&s[n * 144 + ch * 16];
    const uint32_t nb = n0 >> 7;
    const uint32_t nloc = (n0 & 127) + n;
    size_t tile = (size_t)(nb * NKB + kb) * (size_t)B_BYTES;
    *(int4*)(g_qb8 + tile + SWZ(nloc * 128 + ch * 16)) = v;
}

// ===== tcgen05 bf16 GEMM, 256x256 tile, producer/consumer thread split =====
__global__ void __launch_bounds__(256, 1) k_gemm_tc(float* __restrict__ out) {
#if HAS_TCGEN05
    extern __shared__ char smem[];
    const uint32_t sb = smem_u32(smem);
    const uint32_t FULLB = sb;           // 3 x 8B
    const uint32_t EMPTB = sb + 64;      // 3 x 8B
    const uint32_t DONEB = sb + 128;
    const uint32_t TMEMP = sb + 192;
    const uint32_t TILES = (sb + 1024 + 1023) & ~1023u;   // 1024-aligned for SW128
    const int tid = threadIdx.x, wid = tid >> 5, lane = tid & 31;
    const int nb = blockIdx.x, mb = blockIdx.y;

    if (wid == 0) {
        asm volatile("tcgen05.alloc.cta_group::1.sync.aligned.shared::cta.b32 [%0], %1;"
                     :: "r"(TMEMP), "r"(512) : "memory");
        asm volatile("tcgen05.relinquish_alloc_permit.cta_group::1.sync.aligned;");
    }
    if (tid == 0) {
        for (int s = 0; s < TC_NSTAGE; s++) {
            mbar_init(FULLB + 8 * s, 1);
            mbar_init(EMPTB + 8 * s, 1);
        }
        mbar_init(DONEB, 1);
    }
    __syncthreads();
    uint32_t tmem;
    asm volatile("ld.shared.b32 %0, [%1];" : "=r"(tmem) : "r"(TMEMP));

    // f16-kind idesc: dtype=F32(1<<4), atype=BF16(1<<7), btype=BF16(1<<10), N/8@17, M/16@24
    const uint32_t idesc =
        (1u << 4) | (1u << 7) | (1u << 10) | ((TC_BN / 8) << 17) | ((128 / 16) << 24);

    if (tid == 0) {
        // ---- producer: issue all stage loads, gated only by EMPTY ----
        const char* a0 = (const char*)g_qa + (size_t)(2 * mb) * NK64 * A64_BYTES;
        const char* a1 = (const char*)g_qa + (size_t)(2 * mb + 1) * NK64 * A64_BYTES;
        const char* bb = (const char*)g_qb + (size_t)nb * NK64 * B64_BYTES;
        uint32_t epar[TC_NSTAGE] = {0, 0, 0};
        int s = 0;
        for (int rb = 0; rb < NK64; rb++) {
            if (rb >= TC_NSTAGE) { mbar_wait(EMPTB + 8 * s, epar[s]); epar[s] ^= 1; }
            uint32_t st = TILES + s * TC_STAGE_BYTES;
            mbar_expect_tx(FULLB + 8 * s, TC_STAGE_BYTES);
            bulk_g2s(st,                 a0 + (size_t)rb * A64_BYTES, A64_BYTES, FULLB + 8 * s);
            bulk_g2s(st + A64_BYTES,     a1 + (size_t)rb * A64_BYTES, A64_BYTES, FULLB + 8 * s);
            bulk_g2s(st + 2 * A64_BYTES, bb + (size_t)rb * B64_BYTES, B64_BYTES, FULLB + 8 * s);
            s++; if (s == TC_NSTAGE) s = 0;
        }
    } else if (tid == 32) {
        // ---- consumer: wait FULL, issue MMAs, release EMPTY ----
        const uint64_t base = ((uint64_t)2 << 61) | ((uint64_t)1 << 46) | ((uint64_t)64 << 32) |
                              ((uint64_t)1 << 16);
        uint32_t fpar[TC_NSTAGE] = {0, 0, 0};
        int s = 0;
        for (int kb = 0; kb < NK64; kb++) {
            mbar_wait(FULLB + 8 * s, fpar[s]); fpar[s] ^= 1;
            uint32_t st = TILES + s * TC_STAGE_BYTES;
            uint64_t ad0 = base | (uint64_t)((st >> 4) & 0x3FFF);
            uint64_t ad1 = base | (uint64_t)(((st + A64_BYTES) >> 4) & 0x3FFF);
            uint64_t bd  = base | (uint64_t)(((st + 2 * A64_BYTES) >> 4) & 0x3FFF);
#pragma unroll
            for (int j = 0; j < 4; j++) {          // four K=16 steps per k64
                uint32_t en = (uint32_t)((kb | j) != 0);
                asm volatile(
                    "{\n\t.reg .pred p;\n\t"
                    "setp.ne.u32 p, %4, 0;\n\t"
                    "tcgen05.mma.cta_group::1.kind::f16 [%0], %1, %2, %3, p;\n\t}"
                    :: "r"(tmem), "l"(ad0 + j * 2), "l"(bd + j * 2), "r"(idesc), "r"(en)
                    : "memory");
                asm volatile(
                    "{\n\t.reg .pred p;\n\t"
                    "setp.ne.u32 p, %4, 0;\n\t"
                    "tcgen05.mma.cta_group::1.kind::f16 [%0], %1, %2, %3, p;\n\t}"
                    :: "r"(tmem + 256), "l"(ad1 + j * 2), "l"(bd + j * 2), "r"(idesc), "r"(en)
                    : "memory");
            }
            asm volatile("tcgen05.commit.cta_group::1.mbarrier::arrive::one.shared::cluster.b64 [%0];"
                         :: "r"(EMPTB + 8 * s) : "memory");
            s++; if (s == TC_NSTAGE) s = 0;
        }
        asm volatile("tcgen05.commit.cta_group::1.mbarrier::arrive::one.shared::cluster.b64 [%0];"
                     :: "r"(DONEB) : "memory");
    }

    mbar_wait(DONEB, 0);
    asm volatile("tcgen05.fence::after_thread_sync;" ::: "memory");

    // epilogue: WG0 reads D0 (cols 0-255, M rows 0-127); WG1 reads D1 (cols 256-511, rows 128-255)
    const float inv = load_inv();
    const int wg = tid >> 7;                 // 0 or 1
    const uint32_t dbase = tmem + wg * 256;
    const size_t row = (size_t)mb * TC_BM + wg * 128 + (wid & 3) * 32 + lane;
    float* orow = out + row * DIM + (size_t)nb * TC_BN;
#pragma unroll 1
    for (int c8 = 0; c8 < TC_BN / 32; c8++) {
        uint32_t r[32];
        asm volatile(
            "tcgen05.ld.sync.aligned.32x32b.x32.b32 "
            "{%0, %1, %2, %3, %4, %5, %6, %7, "
            " %8, %9, %10, %11, %12, %13, %14, %15, "
            " %16, %17, %18, %19, %20, %21, %22, %23, "
            " %24, %25, %26, %27, %28, %29, %30, %31}, [%32];"
            : "=r"(r[0]), "=r"(r[1]), "=r"(r[2]), "=r"(r[3]),
              "=r"(r[4]), "=r"(r[5]), "=r"(r[6]), "=r"(r[7]),
              "=r"(r[8]), "=r"(r[9]), "=r"(r[10]), "=r"(r[11]),
              "=r"(r[12]), "=r"(r[13]), "=r"(r[14]), "=r"(r[15]),
              "=r"(r[16]), "=r"(r[17]), "=r"(r[18]), "=r"(r[19]),
              "=r"(r[20]), "=r"(r[21]), "=r"(r[22]), "=r"(r[23]),
              "=r"(r[24]), "=r"(r[25]), "=r"(r[26]), "=r"(r[27]),
              "=r"(r[28]), "=r"(r[29]), "=r"(r[30]), "=r"(r[31])
            : "r"(dbase + c8 * 32));
        asm volatile("tcgen05.wait::ld.sync.aligned;" ::: "memory");
#pragma unroll
        for (int i = 0; i < 32; i += 4) {
            float4 v;
            v.x = __uint_as_float(r[i + 0]) * inv;
            v.y = __uint_as_float(r[i + 1]) * inv;
            v.z = __uint_as_float(r[i + 2]) * inv;
            v.w = __uint_as_float(r[i + 3]) * inv;
            *(float4*)(orow + c8 * 32 + i) = v;
        }
    }
    __syncthreads();
    if (wid == 0) {
        asm volatile("tcgen05.dealloc.cta_group::1.sync.aligned.b32 %0, %1;" :: "r"(tmem), "r"(512));
    }
#endif
}

// ================= fallback path (generic pass only) — known-good R2 =================
__global__ void __launch_bounds__(256, 1) k_gemm_mma(float* __restrict__ out) {
#if !HAS_TCGEN05
    extern __shared__ char smem[];
    const uint32_t sb = smem_u32(smem);
    const uint32_t FULLB = sb;
    const uint32_t EMPTB = sb + 64;
    const uint32_t TILES = (sb + 1024 + 1023) & ~1023u;
    const int tid = threadIdx.x, wid = tid >> 5, lane = tid & 31;
    const int nb = blockIdx.x, mb = blockIdx.y;
    const int warp_m = wid & 1, warp_n = wid >> 1;

    if (tid == 0) {
        for (int s = 0; s < STAGES; s++) {
            mbar_init(FULLB + 8 * s, 1);
            mbar_init(EMPTB + 8 * s, 8);
        }
    }
    __syncthreads();

    const int8_t* abase = g_qa8 + (size_t)mb * NKB * A_BYTES;
    const int8_t* bbase = g_qb8 + (size_t)nb * NKB * B_BYTES;

    if (tid == 0) {
#pragma unroll
        for (int p = 0; p < STAGES - 1; p++) {
            uint32_t st = TILES + p * STAGE_BYTES;
            mbar_expect_tx(FULLB + 8 * p, STAGE_BYTES);
            bulk_g2s(st, abase + (size_t)p * A_BYTES, A_BYTES, FULLB + 8 * p);
            bulk_g2s(st + A_BYTES, bbase + (size_t)p * B_BYTES, B_BYTES, FULLB + 8 * p);
        }
    }

    uint32_t preA[4];
#pragma unroll
    for (int mt = 0; mt < 4; mt++) {
        uint32_t row = warp_m * 64 + mt * 16 + (lane & 15);
        preA[mt] = (row * 128) ^ ((row & 7) << 4) ^ ((uint32_t)(lane >> 4) * 16);
    }
    uint32_t preB[2];
#pragma unroll
    for (int np = 0; np < 2; np++) {
        uint32_t n = warp_n * 32 + np * 16 + (lane & 7) + ((lane >> 4) << 3);
        preB[np] = (n * 128) ^ ((n & 7) << 4) ^ ((((uint32_t)lane >> 3) & 1) * 16);
    }

    int acc[4][4][4];
#pragma unroll
    for (int i = 0; i < 4; i++)
#pragma unroll
        for (int j = 0; j < 4; j++)
#pragma unroll
            for (int k = 0; k < 4; k++) acc[i][j][k] = 0;

    for (int kb = 0; kb < NKB; kb++) {
        int s = kb & (STAGES - 1);
        int rb = kb + STAGES - 1;
        if (tid == 0 && rb < NKB) {
            int rs_ = rb & (STAGES - 1);
            if (rb >= STAGES) mbar_wait(EMPTB + 8 * rs_, ((rb / STAGES) - 1) & 1);
            uint32_t st = TILES + rs_ * STAGE_BYTES;
            mbar_expect_tx(FULLB + 8 * rs_, STAGE_BYTES);
            bulk_g2s(st, abase + (size_t)rb * A_BYTES, A_BYTES, FULLB + 8 * rs_);
            bulk_g2s(st + A_BYTES, bbase + (size_t)rb * B_BYTES, B_BYTES, FULLB + 8 * rs_);
        }
        mbar_wait(FULLB + 8 * s, (kb / STAGES) & 1);
        uint32_t As = TILES + s * STAGE_BYTES;
        uint32_t Bs = As + A_BYTES;
#pragma unroll
        for (int c = 0; c < 4; c++) {
            uint32_t koff = (uint32_t)c << 5;
            uint32_t a[4][4], b[2][4];
#pragma unroll
            for (int mt = 0; mt < 4; mt++) ldsm_x4(a[mt], As + (preA[mt] ^ koff));
#pragma unroll
            for (int np = 0; np < 2; np++) ldsm_x4(b[np], Bs + (preB[np] ^ koff));
#pragma unroll
            for (int mt = 0; mt < 4; mt++) {
#pragma unroll
                for (int nt = 0; nt < 4; nt++) {
                    const uint32_t* bp = b[nt >> 1];
                    mma_s8(acc[mt][nt], a[mt], bp[(nt & 1) * 2], bp[(nt & 1) * 2 + 1]);
                }
            }
        }
        if (lane == 0) mbar_arrive(EMPTB + 8 * s);
    }

    const float inv = load_inv();
    const uint32_t r0 = mb * BM + warp_m * 64 + (lane >> 2);
    const uint32_t c0 = nb * BN + warp_n * 32 + (lane & 3) * 2;
#pragma unroll
    for (int mt = 0; mt < 4; mt++) {
#pragma unroll
        for (int nt = 0; nt < 4; nt++) {
            float2 v0, v1;
            v0.x = __int2float_rn(acc[mt][nt][0]) * inv;
            v0.y = __int2float_rn(acc[mt][nt][1]) * inv;
            v1.x = __int2float_rn(acc[mt][nt][2]) * inv;
            v1.y = __int2float_rn(acc[mt][nt][3]) * inv;
            size_t base = (size_t)(r0 + mt * 16) * DIM + c0 + nt * 8;
            *(float2*)(out + base) = v0;
            *(float2*)(out + base + 8 * DIM) = v1;
        }
    }
#endif
}

__device__ int g_has_tc_dev = HAS_TCGEN05;   // 1 in specific pass, 0 in generic

// ---------------- launch ----------------
extern "C" void kernel_launch(void* const* d_in, const int* in_sizes, int n_in,
                              void* d_out, int out_size) {
    (void)in_sizes; (void)n_in; (void)out_size;
    const float* lhs = (const float*)d_in[0];
    const float* rhs = (const float*)d_in[1];
    float* out = (float*)d_out;

    static int has_tc = -1;
    static void* amax_ptr = nullptr;
    if (has_tc < 0) {
        int v = 0;
        cudaMemcpyFromSymbol(&v, g_has_tc_dev, sizeof(int));   // pre-capture call only
        cudaGetSymbolAddress(&amax_ptr, g_amax);
        has_tc = v;
        cudaFuncSetAttribute(k_gemm_mma, cudaFuncAttributeMaxDynamicSharedMemorySize, GEMM_SMEM);
        cudaFuncSetAttribute(k_gemm_tc, cudaFuncAttributeMaxDynamicSharedMemorySize, TC_SMEM);
    }

    cudaMemsetAsync(amax_ptr, 0, 2 * sizeof(unsigned int));
    dim3 ga(1024, 2);
    k_amax2<<<ga, 256>>>((const float4*)lhs, (const float4*)rhs);

    if (has_tc) {
        k_quant_a_bf<<<8192, 256>>>(lhs);
        dim3 gb(DIM / 32, DIM / BK);
        k_quant_b_bf<<<gb, 256>>>(rhs);
        dim3 gt(DIM / TC_BN, DIM / TC_BM);
        k_gemm_tc<<<gt, 256, TC_SMEM>>>(out);
    } else {
        k_quant_a8<<<4096, 256>>>(lhs);
        dim3 gb(DIM / 32, DIM / BK);
        k_quant_b8<<<gb, 256>>>(rhs);
        dim3 gg(DIM / BN, DIM / BM);
        k_gemm_mma<<<gg, 256, GEMM_SMEM>>>(out);
    }
}

// round 12
// speedup vs baseline: 1.2871x; 1.0116x over previous
#include <cuda_runtime.h>
#include <cuda_bf16.h>
#include <cstdint>

// ---- arch capability: tcgen05 legal only in arch/family-specific device pass ----
#if defined(__CUDA_ARCH__) && (defined(__CUDA_ARCH_SPECIFIC__) || defined(__CUDA_ARCH_FAMILY_SPECIFIC__))
#define HAS_TCGEN05 1
#else
#define HAS_TCGEN05 0
#endif

#define DIM 4096
#define NKB 32              // DIM / 128 (quant tile granularity)
#define BK 128

// ---- fallback (mma.sync int8) tiling — known-good R2 path ----
#define BM 128
#define BN 128
#define A_BYTES (BM * BK)
#define B_BYTES (BN * BK)
#define STAGES 4
#define STAGE_BYTES (A_BYTES + B_BYTES)
#define GEMM_SMEM (2048 + STAGES * STAGE_BYTES)

// ---- tcgen05 bf16 tiling: 256x256 tile, BK=64, 3 stages, persistent 2 tiles/CTA ----
#define TC_BM 256
#define TC_BN 256
#define NK64 64                          // DIM / 64
#define A64_BYTES (128 * 64 * 2)         // 16384 per M-half per k64
#define B64_BYTES (256 * 64 * 2)         // 32768 per k64
#define TC_STAGE_BYTES (2 * A64_BYTES + B64_BYTES)   // 65536
#define TC_NSTAGE 3
#define TC_SMEM (2048 + TC_NSTAGE * TC_STAGE_BYTES)  // 198656
#define TC_GRID 128
#define TC_TILES_PER_CTA 2
#define TC_THREADS 320                   // 8 epi warps + producer warp + consumer warp

// legacy per-128 block sizes used by quant layout
#define TCA_BYTES (128 * BK * 2)     // 32768
#define TCB_BYTES (256 * BK * 2)     // 65536

// ---------------- device scratch (static, no allocs) ----------------
__device__ unsigned int g_amax[2];
// bf16 path operands (32MB each)
__device__ __align__(1024) uint16_t g_qa[(size_t)DIM * DIM];
__device__ __align__(1024) uint16_t g_qb[(size_t)DIM * DIM];
// int8 fallback operands
__device__ __align__(1024) int8_t g_qa8[(size_t)DIM * DIM];
__device__ __align__(1024) int8_t g_qb8[(size_t)DIM * DIM];

// ---------------- helpers ----------------
#define SWZ(o) ((o) ^ (((o) >> 3) & 0x70))

__device__ __forceinline__ float load_scale(int slot) {
    return 127.0f / fmaxf(__uint_as_float(g_amax[slot]), 1e-12f);
}
__device__ __forceinline__ float load_inv() {
    float ls = load_scale(0), rs = load_scale(1);
    return 1.0f / (ls * rs);
}

__device__ __forceinline__ uint32_t smem_u32(const void* p) {
    uint32_t a;
    asm("{ .reg .u64 t; cvta.to.shared.u64 t, %1; cvt.u32.u64 %0, t; }" : "=r"(a) : "l"(p));
    return a;
}
__device__ __forceinline__ void mbar_init(uint32_t a, uint32_t cnt) {
    asm volatile("mbarrier.init.shared.b64 [%0], %1;" :: "r"(a), "r"(cnt) : "memory");
}
__device__ __forceinline__ void mbar_expect_tx(uint32_t a, uint32_t bytes) {
    asm volatile("mbarrier.arrive.expect_tx.shared.b64 _, [%0], %1;" :: "r"(a), "r"(bytes) : "memory");
}
__device__ __forceinline__ void mbar_arrive(uint32_t a) {
    asm volatile("mbarrier.arrive.shared.b64 _, [%0];" :: "r"(a) : "memory");
}
__device__ __forceinline__ void mbar_wait(uint32_t a, uint32_t parity) {
    asm volatile(
        "{\n\t.reg .pred P;\n\t"
        "WL_%=:\n\t"
        "mbarrier.try_wait.parity.acquire.cta.shared::cta.b64 P, [%0], %1, 0x989680;\n\t"
        "@P bra.uni WD_%=;\n\t"
        "bra.uni WL_%=;\n\t"
        "WD_%=:\n\t}"
        :: "r"(a), "r"(parity) : "memory");
}
__device__ __forceinline__ void bulk_g2s(uint32_t dst, const void* src, uint32_t bytes, uint32_t mbar) {
    asm volatile("cp.async.bulk.shared::cluster.global.mbarrier::complete_tx::bytes [%0], [%1], %2, [%3];"
                 :: "r"(dst), "l"(src), "r"(bytes), "r"(mbar) : "memory");
}
__device__ __forceinline__ void ldsm_x4(uint32_t* r, uint32_t addr) {
    asm volatile("ldmatrix.sync.aligned.m8n8.x4.shared.b16 {%0,%1,%2,%3}, [%4];"
                 : "=r"(r[0]), "=r"(r[1]), "=r"(r[2]), "=r"(r[3]) : "r"(addr));
}
__device__ __forceinline__ void mma_s8(int* d, const uint32_t* a, uint32_t b0, uint32_t b1) {
    asm volatile(
        "mma.sync.aligned.m16n8k32.row.col.s32.s8.s8.s32 "
        "{%0,%1,%2,%3}, {%4,%5,%6,%7}, {%8,%9}, {%0,%1,%2,%3};"
        : "+r"(d[0]), "+r"(d[1]), "+r"(d[2]), "+r"(d[3])
        : "r"(a[0]), "r"(a[1]), "r"(a[2]), "r"(a[3]), "r"(b0), "r"(b1));
}

// ---------------- pre-pass kernels ----------------
// fused: blockIdx.y selects tensor/slot
__global__ void k_amax2(const float4* __restrict__ a, const float4* __restrict__ b) {
    const float4* x = blockIdx.y ? b : a;
    float m = 0.0f;
    size_t stride = (size_t)gridDim.x * blockDim.x;
    size_t n4 = ((size_t)DIM * DIM) / 4;
    for (size_t j = blockIdx.x * (size_t)blockDim.x + threadIdx.x; j < n4; j += stride) {
        float4 v = x[j];
        m = fmaxf(m, fmaxf(fmaxf(fabsf(v.x), fabsf(v.y)), fmaxf(fabsf(v.z), fabsf(v.w))));
    }
#pragma unroll
    for (int o = 16; o; o >>= 1) m = fmaxf(m, __shfl_xor_sync(0xffffffffu, m, o));
    if ((threadIdx.x & 31) == 0) atomicMax(&g_amax[blockIdx.y], __float_as_uint(m));
}

__device__ __forceinline__ float q8f(float v, float s) {
    float f = rintf(v * s);                      // round-half-even == jnp.round
    return fminf(fmaxf(f, -127.0f), 127.0f);     // exact small integer
}
__device__ __forceinline__ uint16_t bf16_bits(float f) {
    return (uint16_t)__bfloat16_as_ushort(__float2bfloat16_rn(f));
}

// ======== bf16 quant pre-passes (tcgen05 path) ========
// A: [mb128][k64] 16KB blocks: rows r(128) x 64 bf16 (128B rows, SW128)
__global__ void k_quant_a_bf(const float* __restrict__ lhs) {
    const float ls = load_scale(0);
    size_t t = blockIdx.x * (size_t)blockDim.x + threadIdx.x;   // 2M threads, 8 elems each
    size_t e = t * 8;
    uint32_t row = (uint32_t)(e >> 12);
    uint32_t col = (uint32_t)(e & 4095);
    uint32_t mb = row >> 7, r = row & 127;
    uint32_t kb = col >> 7, kl = col & 127;
    uint32_t k64 = kl >> 6, c = kl & 63;
    const float4* src = (const float4*)(lhs + e);
    float4 v0 = src[0], v1 = src[1];
    union { uint16_t q[8]; int4 p; } u;
    u.q[0] = bf16_bits(q8f(v0.x, ls)); u.q[1] = bf16_bits(q8f(v0.y, ls));
    u.q[2] = bf16_bits(q8f(v0.z, ls)); u.q[3] = bf16_bits(q8f(v0.w, ls));
    u.q[4] = bf16_bits(q8f(v1.x, ls)); u.q[5] = bf16_bits(q8f(v1.y, ls));
    u.q[6] = bf16_bits(q8f(v1.z, ls)); u.q[7] = bf16_bits(q8f(v1.w, ls));
    size_t off = (size_t)(mb * NKB + kb) * TCA_BYTES + k64 * 16384 + SWZ(r * 128 + c * 2);
    *(int4*)((char*)g_qa + off) = u.p;
}

// B: [nb256][k64] 32KB blocks: rows n(256) x 64 bf16 (SW128)
__global__ void k_quant_b_bf(const float* __restrict__ rhs) {
    __shared__ __align__(16) uint16_t s[32][136];   // [n][k] bf16, padded
    const float rsc = load_scale(1);
    const uint32_t n0 = blockIdx.x * 32;
    const uint32_t kb = blockIdx.y;
    const uint32_t k0 = kb * 128;
    const int tid = threadIdx.x;           // 256 threads
    const int wp = tid >> 5, lane = tid & 31;
#pragma unroll
    for (int kk = wp; kk < 128; kk += 8) {
        float v = rhs[(size_t)(k0 + kk) * DIM + n0 + lane];
        s[lane][kk] = bf16_bits(q8f(v, rsc));
    }
    __syncthreads();
    const uint32_t nb = n0 >> 8;
    const size_t tile = (size_t)(nb * NKB + kb) * TCB_BYTES;
#pragma unroll
    for (int it = 0; it < 2; it++) {
        int idx = tid + it * 256;          // 0..511
        int n = idx >> 4;                  // 0..31
        int c16 = idx & 15;                // 16B chunk along k
        int4 v = *(int4*)&s[n][c16 * 8];
        uint32_t k64 = c16 >> 3, cb = (c16 & 7) * 16;
        uint32_t nrow = (n0 & 255) + n;
        *(int4*)((char*)g_qb + tile + k64 * 32768 + SWZ(nrow * 128 + cb)) = v;
    }
}

// ======== int8 quant pre-passes (fallback path) ========
__global__ void k_quant_a8(const float* __restrict__ lhs) {
    const float ls = load_scale(0);
    size_t t = blockIdx.x * (size_t)blockDim.x + threadIdx.x;
    size_t e = t * 16;
    uint32_t row = (uint32_t)(e >> 12);
    uint32_t col = (uint32_t)(e & 4095);
    uint32_t mb = row >> 7, r = row & 127;
    uint32_t kb = col >> 7, c = col & 127;
    const float4* src = (const float4*)(lhs + e);
    int4 packed;
    int8_t* q = (int8_t*)&packed;
#pragma unroll
    for (int i = 0; i < 4; i++) {
        float4 v = src[i];
        q[i * 4 + 0] = (int8_t)q8f(v.x, ls);
        q[i * 4 + 1] = (int8_t)q8f(v.y, ls);
        q[i * 4 + 2] = (int8_t)q8f(v.z, ls);
        q[i * 4 + 3] = (int8_t)q8f(v.w, ls);
    }
    size_t tile = (size_t)(mb * NKB + kb) * (size_t)A_BYTES;
    *(int4*)(g_qa8 + tile + SWZ(r * 128 + c)) = packed;
}

__global__ void k_quant_b8(const float* __restrict__ rhs) {
    __shared__ int8_t s[32 * 144];
    const float rsc = load_scale(1);
    const uint32_t n0 = blockIdx.x * 32;
    const uint32_t kb = blockIdx.y;
    const uint32_t k0 = kb * 128;
    const int tid = threadIdx.x;
    const int wp = tid >> 5, lane = tid & 31;
#pragma unroll
    for (int kk = wp; kk < 128; kk += 8) {
        float v = rhs[(size_t)(k0 + kk) * DIM + n0 + lane];
        s[lane * 144 + kk] = (int8_t)q8f(v, rsc);
    }
    __syncthreads();
    const uint32_t n = tid >> 3, ch = tid & 7;
    int4 v = *(int4*)&s[n * 144 + ch * 16];
    const uint32_t nb = n0 >> 7;
    const uint32_t nloc = (n0 & 127) + n;
    size_t tile = (size_t)(nb * NKB + kb) * (size_t)B_BYTES;
    *(int4*)(g_qb8 + tile + SWZ(nloc * 128 + ch * 16)) = v;
}

// ===== tcgen05 bf16 GEMM: persistent, 2 tiles/CTA, warp-specialized =====
__global__ void __launch_bounds__(TC_THREADS, 1) k_gemm_tc(float* __restrict__ out) {
#if HAS_TCGEN05
    extern __shared__ char smem[];
    const uint32_t sb = smem_u32(smem);
    const uint32_t FULLB = sb;           // 3 x 8B
    const uint32_t EMPTB = sb + 64;      // 3 x 8B
    const uint32_t DONEB = sb + 128;
    const uint32_t EPIB  = sb + 136;
    const uint32_t TMEMP = sb + 192;
    const uint32_t TILES = (sb + 1024 + 1023) & ~1023u;   // 1024-aligned for SW128
    const int tid = threadIdx.x, wid = tid >> 5, lane = tid & 31;
    const int bid = blockIdx.x;          // 0..127

    if (wid == 0) {
        asm volatile("tcgen05.alloc.cta_group::1.sync.aligned.shared::cta.b32 [%0], %1;"
                     :: "r"(TMEMP), "r"(512) : "memory");
        asm volatile("tcgen05.relinquish_alloc_permit.cta_group::1.sync.aligned;");
    }
    if (tid == 0) {
        for (int s = 0; s < TC_NSTAGE; s++) {
            mbar_init(FULLB + 8 * s, 1);
            mbar_init(EMPTB + 8 * s, 1);
        }
        mbar_init(DONEB, 1);
        mbar_init(EPIB, 8);              // one arrive per epilogue warp
    }
    __syncthreads();
    uint32_t tmem;
    asm volatile("ld.shared.b32 %0, [%1];" : "=r"(tmem) : "r"(TMEMP));

    // f16-kind idesc: dtype=F32(1<<4), atype=BF16(1<<7), btype=BF16(1<<10), N/8@17, M/16@24
    const uint32_t idesc =
        (1u << 4) | (1u << 7) | (1u << 10) | ((TC_BN / 8) << 17) | ((128 / 16) << 24);

    if (tid == 256) {
        // ---- producer warp (lane 0): continuous stage ring across both tiles ----
        uint32_t epar[TC_NSTAGE] = {0, 0, 0};
        int s = 0, cnt = 0;
#pragma unroll 1
        for (int ti = 0; ti < TC_TILES_PER_CTA; ti++) {
            int t = bid + ti * TC_GRID;
            int nb = t & 15, mb = t >> 4;
            const char* a0 = (const char*)g_qa + (size_t)(2 * mb) * NK64 * A64_BYTES;
            const char* a1 = (const char*)g_qa + (size_t)(2 * mb + 1) * NK64 * A64_BYTES;
            const char* bb = (const char*)g_qb + (size_t)nb * NK64 * B64_BYTES;
#pragma unroll 1
            for (int rb = 0; rb < NK64; rb++, cnt++) {
                if (cnt >= TC_NSTAGE) { mbar_wait(EMPTB + 8 * s, epar[s]); epar[s] ^= 1; }
                uint32_t st = TILES + s * TC_STAGE_BYTES;
                mbar_expect_tx(FULLB + 8 * s, TC_STAGE_BYTES);
                bulk_g2s(st,                 a0 + (size_t)rb * A64_BYTES, A64_BYTES, FULLB + 8 * s);
                bulk_g2s(st + A64_BYTES,     a1 + (size_t)rb * A64_BYTES, A64_BYTES, FULLB + 8 * s);
                bulk_g2s(st + 2 * A64_BYTES, bb + (size_t)rb * B64_BYTES, B64_BYTES, FULLB + 8 * s);
                s++; if (s == TC_NSTAGE) s = 0;
            }
        }
    } else if (tid == 288) {
        // ---- consumer warp (lane 0): MMAs; TMEM reuse gated by EPIB ----
        const uint64_t base = ((uint64_t)2 << 61) | ((uint64_t)1 << 46) | ((uint64_t)64 << 32) |
                              ((uint64_t)1 << 16);
        uint32_t fpar[TC_NSTAGE] = {0, 0, 0};
        int s = 0;
#pragma unroll 1
        for (int ti = 0; ti < TC_TILES_PER_CTA; ti++) {
#pragma unroll 1
            for (int kb = 0; kb < NK64; kb++) {
                mbar_wait(FULLB + 8 * s, fpar[s]); fpar[s] ^= 1;
                if (ti > 0 && kb == 0) mbar_wait(EPIB, (uint32_t)(ti - 1) & 1);
                uint32_t st = TILES + s * TC_STAGE_BYTES;
                uint64_t ad0 = base | (uint64_t)((st >> 4) & 0x3FFF);
                uint64_t ad1 = base | (uint64_t)(((st + A64_BYTES) >> 4) & 0x3FFF);
                uint64_t bd  = base | (uint64_t)(((st + 2 * A64_BYTES) >> 4) & 0x3FFF);
#pragma unroll
                for (int j = 0; j < 4; j++) {          // four K=16 steps per k64
                    uint32_t en = (uint32_t)((kb | j) != 0);
                    asm volatile(
                        "{\n\t.reg .pred p;\n\t"
                        "setp.ne.u32 p, %4, 0;\n\t"
                        "tcgen05.mma.cta_group::1.kind::f16 [%0], %1, %2, %3, p;\n\t}"
                        :: "r"(tmem), "l"(ad0 + j * 2), "l"(bd + j * 2), "r"(idesc), "r"(en)
                        : "memory");
                    asm volatile(
                        "{\n\t.reg .pred p;\n\t"
                        "setp.ne.u32 p, %4, 0;\n\t"
                        "tcgen05.mma.cta_group::1.kind::f16 [%0], %1, %2, %3, p;\n\t}"
                        :: "r"(tmem + 256), "l"(ad1 + j * 2), "l"(bd + j * 2), "r"(idesc), "r"(en)
                        : "memory");
                }
                asm volatile("tcgen05.commit.cta_group::1.mbarrier::arrive::one.shared::cluster.b64 [%0];"
                             :: "r"(EMPTB + 8 * s) : "memory");
                s++; if (s == TC_NSTAGE) s = 0;
            }
            asm volatile("tcgen05.commit.cta_group::1.mbarrier::arrive::one.shared::cluster.b64 [%0];"
                         :: "r"(DONEB) : "memory");
        }
    } else if (tid < 256) {
        // ---- epilogue warps 0-7 ----
        const float inv = load_inv();
        const int wg = tid >> 7;                 // 0 or 1
        const uint32_t dbase = tmem + wg * 256;
#pragma unroll 1
        for (int ti = 0; ti < TC_TILES_PER_CTA; ti++) {
            int t = bid + ti * TC_GRID;
            int nb = t & 15, mb = t >> 4;
            mbar_wait(DONEB, (uint32_t)ti & 1);
            asm volatile("tcgen05.fence::after_thread_sync;" ::: "memory");
            const size_t row = (size_t)mb * TC_BM + wg * 128 + (wid & 3) * 32 + lane;
            float* orow = out + row * DIM + (size_t)nb * TC_BN;
#pragma unroll 1
            for (int c8 = 0; c8 < TC_BN / 32; c8++) {
                uint32_t r[32];
                asm volatile(
                    "tcgen05.ld.sync.aligned.32x32b.x32.b32 "
                    "{%0, %1, %2, %3, %4, %5, %6, %7, "
                    " %8, %9, %10, %11, %12, %13, %14, %15, "
                    " %16, %17, %18, %19, %20, %21, %22, %23, "
                    " %24, %25, %26, %27, %28, %29, %30, %31}, [%32];"
                    : "=r"(r[0]), "=r"(r[1]), "=r"(r[2]), "=r"(r[3]),
                      "=r"(r[4]), "=r"(r[5]), "=r"(r[6]), "=r"(r[7]),
                      "=r"(r[8]), "=r"(r[9]), "=r"(r[10]), "=r"(r[11]),
                      "=r"(r[12]), "=r"(r[13]), "=r"(r[14]), "=r"(r[15]),
                      "=r"(r[16]), "=r"(r[17]), "=r"(r[18]), "=r"(r[19]),
                      "=r"(r[20]), "=r"(r[21]), "=r"(r[22]), "=r"(r[23]),
                      "=r"(r[24]), "=r"(r[25]), "=r"(r[26]), "=r"(r[27]),
                      "=r"(r[28]), "=r"(r[29]), "=r"(r[30]), "=r"(r[31])
                    : "r"(dbase + c8 * 32));
                asm volatile("tcgen05.wait::ld.sync.aligned;" ::: "memory");
#pragma unroll
                for (int i = 0; i < 32; i += 4) {
                    float4 v;
                    v.x = __uint_as_float(r[i + 0]) * inv;
                    v.y = __uint_as_float(r[i + 1]) * inv;
                    v.z = __uint_as_float(r[i + 2]) * inv;
                    v.w = __uint_as_float(r[i + 3]) * inv;
                    *(float4*)(orow + c8 * 32 + i) = v;
                }
            }
            // this warp is done reading TMEM for tile ti
            if (lane == 0) mbar_arrive(EPIB);
        }
        // all epilogue warps done with TMEM -> dealloc
        asm volatile("bar.sync 1, 256;" ::: "memory");
        if (wid == 0) {
            asm volatile("tcgen05.dealloc.cta_group::1.sync.aligned.b32 %0, %1;" :: "r"(tmem), "r"(512));
        }
    }
#endif
}

// ================= fallback path (generic pass only) — known-good R2 =================
__global__ void __launch_bounds__(256, 1) k_gemm_mma(float* __restrict__ out) {
#if !HAS_TCGEN05
    extern __shared__ char smem[];
    const uint32_t sb = smem_u32(smem);
    const uint32_t FULLB = sb;
    const uint32_t EMPTB = sb + 64;
    const uint32_t TILES = (sb + 1024 + 1023) & ~1023u;
    const int tid = threadIdx.x, wid = tid >> 5, lane = tid & 31;
    const int nb = blockIdx.x, mb = blockIdx.y;
    const int warp_m = wid & 1, warp_n = wid >> 1;

    if (tid == 0) {
        for (int s = 0; s < STAGES; s++) {
            mbar_init(FULLB + 8 * s, 1);
            mbar_init(EMPTB + 8 * s, 8);
        }
    }
    __syncthreads();

    const int8_t* abase = g_qa8 + (size_t)mb * NKB * A_BYTES;
    const int8_t* bbase = g_qb8 + (size_t)nb * NKB * B_BYTES;

    if (tid == 0) {
#pragma unroll
        for (int p = 0; p < STAGES - 1; p++) {
            uint32_t st = TILES + p * STAGE_BYTES;
            mbar_expect_tx(FULLB + 8 * p, STAGE_BYTES);
            bulk_g2s(st, abase + (size_t)p * A_BYTES, A_BYTES, FULLB + 8 * p);
            bulk_g2s(st + A_BYTES, bbase + (size_t)p * B_BYTES, B_BYTES, FULLB + 8 * p);
        }
    }

    uint32_t preA[4];
#pragma unroll
    for (int mt = 0; mt < 4; mt++) {
        uint32_t row = warp_m * 64 + mt * 16 + (lane & 15);
        preA[mt] = (row * 128) ^ ((row & 7) << 4) ^ ((uint32_t)(lane >> 4) * 16);
    }
    uint32_t preB[2];
#pragma unroll
    for (int np = 0; np < 2; np++) {
        uint32_t n = warp_n * 32 + np * 16 + (lane & 7) + ((lane >> 4) << 3);
        preB[np] = (n * 128) ^ ((n & 7) << 4) ^ ((((uint32_t)lane >> 3) & 1) * 16);
    }

    int acc[4][4][4];
#pragma unroll
    for (int i = 0; i < 4; i++)
#pragma unroll
        for (int j = 0; j < 4; j++)
#pragma unroll
            for (int k = 0; k < 4; k++) acc[i][j][k] = 0;

    for (int kb = 0; kb < NKB; kb++) {
        int s = kb & (STAGES - 1);
        int rb = kb + STAGES - 1;
        if (tid == 0 && rb < NKB) {
            int rs_ = rb & (STAGES - 1);
            if (rb >= STAGES) mbar_wait(EMPTB + 8 * rs_, ((rb / STAGES) - 1) & 1);
            uint32_t st = TILES + rs_ * STAGE_BYTES;
            mbar_expect_tx(FULLB + 8 * rs_, STAGE_BYTES);
            bulk_g2s(st, abase + (size_t)rb * A_BYTES, A_BYTES, FULLB + 8 * rs_);
            bulk_g2s(st + A_BYTES, bbase + (size_t)rb * B_BYTES, B_BYTES, FULLB + 8 * rs_);
        }
        mbar_wait(FULLB + 8 * s, (kb / STAGES) & 1);
        uint32_t As = TILES + s * STAGE_BYTES;
        uint32_t Bs = As + A_BYTES;
#pragma unroll
        for (int c = 0; c < 4; c++) {
            uint32_t koff = (uint32_t)c << 5;
            uint32_t a[4][4], b[2][4];
#pragma unroll
            for (int mt = 0; mt < 4; mt++) ldsm_x4(a[mt], As + (preA[mt] ^ koff));
#pragma unroll
            for (int np = 0; np < 2; np++) ldsm_x4(b[np], Bs + (preB[np] ^ koff));
#pragma unroll
            for (int mt = 0; mt < 4; mt++) {
#pragma unroll
                for (int nt = 0; nt < 4; nt++) {
                    const uint32_t* bp = b[nt >> 1];
                    mma_s8(acc[mt][nt], a[mt], bp[(nt & 1) * 2], bp[(nt & 1) * 2 + 1]);
                }
            }
        }
        if (lane == 0) mbar_arrive(EMPTB + 8 * s);
    }

    const float inv = load_inv();
    const uint32_t r0 = mb * BM + warp_m * 64 + (lane >> 2);
    const uint32_t c0 = nb * BN + warp_n * 32 + (lane & 3) * 2;
#pragma unroll
    for (int mt = 0; mt < 4; mt++) {
#pragma unroll
        for (int nt = 0; nt < 4; nt++) {
            float2 v0, v1;
            v0.x = __int2float_rn(acc[mt][nt][0]) * inv;
            v0.y = __int2float_rn(acc[mt][nt][1]) * inv;
            v1.x = __int2float_rn(acc[mt][nt][2]) * inv;
            v1.y = __int2float_rn(acc[mt][nt][3]) * inv;
            size_t base = (size_t)(r0 + mt * 16) * DIM + c0 + nt * 8;
            *(float2*)(out + base) = v0;
            *(float2*)(out + base + 8 * DIM) = v1;
        }
    }
#endif
}

__device__ int g_has_tc_dev = HAS_TCGEN05;   // 1 in specific pass, 0 in generic

// ---------------- launch ----------------
extern "C" void kernel_launch(void* const* d_in, const int* in_sizes, int n_in,
                              void* d_out, int out_size) {
    (void)in_sizes; (void)n_in; (void)out_size;
    const float* lhs = (const float*)d_in[0];
    const float* rhs = (const float*)d_in[1];
    float* out = (float*)d_out;

    static int has_tc = -1;
    static void* amax_ptr = nullptr;
    if (has_tc < 0) {
        int v = 0;
        cudaMemcpyFromSymbol(&v, g_has_tc_dev, sizeof(int));   // pre-capture call only
        cudaGetSymbolAddress(&amax_ptr, g_amax);
        has_tc = v;
        cudaFuncSetAttribute(k_gemm_mma, cudaFuncAttributeMaxDynamicSharedMemorySize, GEMM_SMEM);
        cudaFuncSetAttribute(k_gemm_tc, cudaFuncAttributeMaxDynamicSharedMemorySize, TC_SMEM);
    }

    cudaMemsetAsync(amax_ptr, 0, 2 * sizeof(unsigned int));
    dim3 ga(1024, 2);
    k_amax2<<<ga, 256>>>((const float4*)lhs, (const float4*)rhs);

    if (has_tc) {
        k_quant_a_bf<<<8192, 256>>>(lhs);
        dim3 gb(DIM / 32, DIM / BK);
        k_quant_b_bf<<<gb, 256>>>(rhs);
        k_gemm_tc<<<TC_GRID, TC_THREADS, TC_SMEM>>>(out);
    } else {
        k_quant_a8<<<4096, 256>>>(lhs);
        dim3 gb(DIM / 32, DIM / BK);
        k_quant_b8<<<gb, 256>>>(rhs);
        dim3 gg(DIM / BN, DIM / BM);
        k_gemm_mma<<<gg, 256, GEMM_SMEM>>>(out);
    }
}